// round 9
// baseline (speedup 1.0000x reference)
#include <cuda_runtime.h>
#include <math.h>

// Problem dims (fixed by the reference)
#define B_  1024
#define D_  512
#define H_  2048
#define NSTEPS 16

// -------- device scratch (allocation-free: static __device__ globals) --------
__device__ float    g_y   [B_ * D_];      // current state y (exact fp32)
__device__ float    g_yr  [B_ * D_];      // RNA-tf32-rounded copy of y (MMA input)
__device__ float    g_ytmp[B_ * D_];      // RNA-rounded y + c*k (MMA input)
__device__ float    g_acc [B_ * D_];      // RK4 accumulator (exact fp32)
__device__ float    g_h   [B_ * H_];      // RNA-rounded tanh activations
__device__ float    g_W1r [D_ * H_];      // RNA-rounded W1
__device__ float    g_W2r [H_ * D_];      // RNA-rounded W2
__device__ float    g_part[4][B_ * D_];   // split-K partials for GEMM2
__device__ unsigned g_cnt [64];           // split-K fixup counters (16 y x 4 x)

// ---------------------------------------------------------------------------
__device__ __forceinline__ float rna_tf32(float x) {
    unsigned r;
    asm("cvt.rna.tf32.f32 %0, %1;" : "=r"(r) : "f"(x));
    return __uint_as_float(r);
}
__device__ __forceinline__ float fast_tanh(float x) {
    float y;
    asm("tanh.approx.f32 %0, %1;" : "=f"(y) : "f"(x));
    return y;
}
// mma.sync m16n8k8 tf32: D = A@B + C, fp32 accumulate. Inputs already tf32-exact.
__device__ __forceinline__ void mma_tf32(float* c, const unsigned* a, const unsigned* b) {
    asm volatile(
        "mma.sync.aligned.m16n8k8.row.col.f32.tf32.tf32.f32 "
        "{%0,%1,%2,%3}, {%4,%5,%6,%7}, {%8,%9}, {%0,%1,%2,%3};"
        : "+f"(c[0]), "+f"(c[1]), "+f"(c[2]), "+f"(c[3])
        : "r"(a[0]), "r"(a[1]), "r"(a[2]), "r"(a[3]),
          "r"(b[0]), "r"(b[1]));
}
__device__ __forceinline__ void cp_async16(float* smem_dst, const float* gmem_src) {
    unsigned s = (unsigned)__cvta_generic_to_shared(smem_dst);
    asm volatile("cp.async.ca.shared.global [%0], [%1], 16;\n" :: "r"(s), "l"(gmem_src));
}
__device__ __forceinline__ void cp_commit() {
    asm volatile("cp.async.commit_group;\n");
}
template <int N>
__device__ __forceinline__ void cp_wait() {
    asm volatile("cp.async.wait_group %0;\n" :: "n"(N));
}

// ---------------------------------------------------------------------------
__global__ void init_y_kernel(const float* __restrict__ x) {
    int i = blockIdx.x * blockDim.x + threadIdx.x;
    if (i < B_ * D_) {
        float v = x[i];
        g_y[i]  = v;
        g_yr[i] = rna_tf32(v);
    }
}
__global__ void prep_weights_kernel(const float* __restrict__ W1,
                                    const float* __restrict__ W2) {
    int i = blockIdx.x * blockDim.x + threadIdx.x;
    if (i < D_ * H_) {
        g_W1r[i] = rna_tf32(W1[i]);
        g_W2r[i] = rna_tf32(W2[i]);
    }
}

// ---------------------------------------------------------------------------
// GEMM1 (unchanged, ~13us):
//   g_h[1024,2048] = rna( tanh( Ain[1024,512] @ W1r + b1 + t ) )
//   CTA 64x128, BK=16, 256 threads = 8 warps (2M x 4N), warp tile 32x32.
//   3-stage single-sync cp.async. Grid (16,16)=256.
__global__ __launch_bounds__(256) void gemm1_tanh(
    const float* __restrict__ b1, float t, int in_sel)
{
    __shared__ float As[3][64 * 20];
    __shared__ float Bs[3][16 * 136];

    const float* __restrict__ Ain = in_sel ? g_ytmp : g_yr;
    const float* __restrict__ W1  = g_W1r;

    const int tid  = threadIdx.x;
    const int lane = tid & 31;
    const int warp = tid >> 5;
    const int g    = lane >> 2;
    const int t4   = lane & 3;
    const int wm   = warp & 1;      // m offset wm*32
    const int wn   = warp >> 1;     // n offset wn*32

    const int bn0 = blockIdx.x * 128;
    const int bm0 = blockIdx.y * 64;

    const int ar = tid >> 2, ac = (tid & 3) * 4;
    auto load_slab = [&](int k0, int s) {
        cp_async16(&As[s][ar * 20 + ac], &Ain[(size_t)(bm0 + ar) * D_ + k0 + ac]);
#pragma unroll
        for (int i = 0; i < 2; i++) {
            int id = tid + 256 * i;
            int r = id >> 5, c = (id & 31) * 4;
            cp_async16(&Bs[s][r * 136 + c], &W1[(size_t)(k0 + r) * H_ + bn0 + c]);
        }
        cp_commit();
    };

    float c[2][4][4];
#pragma unroll
    for (int i = 0; i < 2; i++)
#pragma unroll
        for (int j = 0; j < 4; j++)
#pragma unroll
            for (int e = 0; e < 4; e++) c[i][j][e] = 0.f;

    const int NS = D_ / 16;   // 32 slabs
    load_slab(0, 0);
    load_slab(16, 1);

    for (int si = 0; si < NS; si++) {
        if (si + 1 < NS) cp_wait<1>(); else cp_wait<0>();
        __syncthreads();
        if (si + 2 < NS) load_slab((si + 2) * 16, (si + 2) % 3);

        const unsigned* Asu = reinterpret_cast<const unsigned*>(As[si % 3]);
        const unsigned* Bsu = reinterpret_cast<const unsigned*>(Bs[si % 3]);
#pragma unroll
        for (int kk = 0; kk < 16; kk += 8) {
            unsigned a[2][4], b[4][2];
#pragma unroll
            for (int mt = 0; mt < 2; mt++) {
                int m0 = wm * 32 + mt * 16 + g;
                a[mt][0] = Asu[(m0)     * 20 + kk + t4];
                a[mt][1] = Asu[(m0 + 8) * 20 + kk + t4];
                a[mt][2] = Asu[(m0)     * 20 + kk + t4 + 4];
                a[mt][3] = Asu[(m0 + 8) * 20 + kk + t4 + 4];
            }
#pragma unroll
            for (int nt = 0; nt < 4; nt++) {
                int n0 = wn * 32 + nt * 8 + g;
                b[nt][0] = Bsu[(kk + t4)     * 136 + n0];
                b[nt][1] = Bsu[(kk + t4 + 4) * 136 + n0];
            }
#pragma unroll
            for (int mt = 0; mt < 2; mt++)
#pragma unroll
                for (int nt = 0; nt < 4; nt++)
                    mma_tf32(c[mt][nt], a[mt], b[nt]);
        }
    }

    // epilogue: rna(tanh(c + b1[n] + t)) -> g_h
#pragma unroll
    for (int mt = 0; mt < 2; mt++) {
        int row0 = bm0 + wm * 32 + mt * 16 + g;
#pragma unroll
        for (int nt = 0; nt < 4; nt++) {
            int col = bn0 + wn * 32 + nt * 8 + 2 * t4;
            float bb0 = b1[col] + t, bb1 = b1[col + 1] + t;
            float2 v0, v1;
            v0.x = rna_tf32(fast_tanh(c[mt][nt][0] + bb0));
            v0.y = rna_tf32(fast_tanh(c[mt][nt][1] + bb1));
            v1.x = rna_tf32(fast_tanh(c[mt][nt][2] + bb0));
            v1.y = rna_tf32(fast_tanh(c[mt][nt][3] + bb1));
            *reinterpret_cast<float2*>(&g_h[(size_t)row0 * H_ + col])       = v0;
            *reinterpret_cast<float2*>(&g_h[(size_t)(row0 + 8) * H_ + col]) = v1;
        }
    }
}

// ---------------------------------------------------------------------------
// GEMM2 split-K x4 with FUSED RK4 fixup epilogue:
//   partial[z] = g_h[:, z*512:(z+1)*512] @ W2r-slice; the LAST CTA to finish
//   a given (x,y) output tile sums the 4 partials + b2 and applies the RK4
//   stage update for that 64x128 tile (CUTLASS-style split-K semaphore).
//   CTA 64(M)x128(N), K-slice 512, BK=16, 256 threads, warp tile 32x32.
//   Grid (4,16,4) = 256 CTAs.
// mode: 0 k1 / 1 k2 / 2 k3 / 3 k4 / 4 k4-final(write d_out)
__global__ __launch_bounds__(256) void gemm2_splitk(
    const float* __restrict__ b2, float dt, int mode, float* __restrict__ yout)
{
    __shared__ float As[3][64 * 20];
    __shared__ float Bs[3][16 * 136];
    __shared__ int s_last;

    const float* __restrict__ W2 = g_W2r;

    const int tid  = threadIdx.x;
    const int lane = tid & 31;
    const int warp = tid >> 5;
    const int g    = lane >> 2;
    const int t4   = lane & 3;
    const int wm   = warp & 1;      // m offset wm*32
    const int wn   = warp >> 1;     // n offset wn*32

    const int bn0 = blockIdx.x * 128;
    const int bm0 = blockIdx.y * 64;
    const int kb  = blockIdx.z * (H_ / 4);   // K-slice base

    const int ar = tid >> 2, ac = (tid & 3) * 4;
    auto load_slab = [&](int k0, int s) {
        cp_async16(&As[s][ar * 20 + ac],
                   &g_h[(size_t)(bm0 + ar) * H_ + kb + k0 + ac]);
#pragma unroll
        for (int i = 0; i < 2; i++) {
            int id = tid + 256 * i;
            int r = id >> 5, c = (id & 31) * 4;
            cp_async16(&Bs[s][r * 136 + c],
                       &W2[(size_t)(kb + k0 + r) * D_ + bn0 + c]);
        }
        cp_commit();
    };

    float c[2][4][4];
#pragma unroll
    for (int i = 0; i < 2; i++)
#pragma unroll
        for (int j = 0; j < 4; j++)
#pragma unroll
            for (int e = 0; e < 4; e++) c[i][j][e] = 0.f;

    const int NS = (H_ / 4) / 16;   // 32 slabs
    load_slab(0, 0);
    load_slab(16, 1);

    for (int si = 0; si < NS; si++) {
        if (si + 1 < NS) cp_wait<1>(); else cp_wait<0>();
        __syncthreads();
        if (si + 2 < NS) load_slab((si + 2) * 16, (si + 2) % 3);

        const unsigned* Asu = reinterpret_cast<const unsigned*>(As[si % 3]);
        const unsigned* Bsu = reinterpret_cast<const unsigned*>(Bs[si % 3]);
#pragma unroll
        for (int kk = 0; kk < 16; kk += 8) {
            unsigned a[2][4], b[4][2];
#pragma unroll
            for (int mt = 0; mt < 2; mt++) {
                int m0 = wm * 32 + mt * 16 + g;
                a[mt][0] = Asu[(m0)     * 20 + kk + t4];
                a[mt][1] = Asu[(m0 + 8) * 20 + kk + t4];
                a[mt][2] = Asu[(m0)     * 20 + kk + t4 + 4];
                a[mt][3] = Asu[(m0 + 8) * 20 + kk + t4 + 4];
            }
#pragma unroll
            for (int nt = 0; nt < 4; nt++) {
                int n0 = wn * 32 + nt * 8 + g;
                b[nt][0] = Bsu[(kk + t4)     * 136 + n0];
                b[nt][1] = Bsu[(kk + t4 + 4) * 136 + n0];
            }
#pragma unroll
            for (int mt = 0; mt < 2; mt++)
#pragma unroll
                for (int nt = 0; nt < 4; nt++)
                    mma_tf32(c[mt][nt], a[mt], b[nt]);
        }
    }

    // write raw partial tile
    float* __restrict__ P = g_part[blockIdx.z];
#pragma unroll
    for (int mt = 0; mt < 2; mt++) {
        int row0 = bm0 + wm * 32 + mt * 16 + g;
#pragma unroll
        for (int nt = 0; nt < 4; nt++) {
            int col = bn0 + wn * 32 + nt * 8 + 2 * t4;
            *reinterpret_cast<float2*>(&P[(size_t)row0 * D_ + col]) =
                make_float2(c[mt][nt][0], c[mt][nt][1]);
            *reinterpret_cast<float2*>(&P[(size_t)(row0 + 8) * D_ + col]) =
                make_float2(c[mt][nt][2], c[mt][nt][3]);
        }
    }

    // ---- split-K fixup: last CTA per (x,y) tile applies the RK4 epilogue ----
    __syncthreads();
    if (tid == 0) {
        __threadfence();   // release: partial writes (all threads, ordered by
                           // the bar.sync above; fences are cumulative)
        unsigned old = atomicAdd(&g_cnt[blockIdx.y * 4 + blockIdx.x], 1u);
        s_last = ((old & 3u) == 3u);
    }
    __syncthreads();
    if (!s_last) return;
    __threadfence();       // acquire: make all 4 slices' partials visible

    const float half_dt  = 0.5f * dt;
    const float sixth_dt = dt * (1.0f / 6.0f);

    // tile = rows [bm0, bm0+64) x cols [bn0, bn0+128): 2048 float4, 8 per thread
#pragma unroll
    for (int j = 0; j < 8; j++) {
        int f   = tid + j * 256;          // 0..2047
        int r   = f >> 5;                 // 0..63
        int c4  = f & 31;                 // 0..31
        int row = bm0 + r;
        int col = bn0 + c4 * 4;
        size_t i = (size_t)row * D_ + col;

        float4 p0 = *reinterpret_cast<const float4*>(&g_part[0][i]);
        float4 p1 = *reinterpret_cast<const float4*>(&g_part[1][i]);
        float4 p2 = *reinterpret_cast<const float4*>(&g_part[2][i]);
        float4 p3 = *reinterpret_cast<const float4*>(&g_part[3][i]);
        float4 bb = *reinterpret_cast<const float4*>(&b2[col]);

        float kv[4];
        kv[0] = p0.x + p1.x + p2.x + p3.x + bb.x;
        kv[1] = p0.y + p1.y + p2.y + p3.y + bb.y;
        kv[2] = p0.z + p1.z + p2.z + p3.z + bb.z;
        kv[3] = p0.w + p1.w + p2.w + p3.w + bb.w;

        float4 y = *reinterpret_cast<const float4*>(&g_y[i]);

        if (mode == 0) {
            float4 acv, yt;
            acv.x = kv[0]; acv.y = kv[1]; acv.z = kv[2]; acv.w = kv[3];
            yt.x = rna_tf32(y.x + half_dt * kv[0]);
            yt.y = rna_tf32(y.y + half_dt * kv[1]);
            yt.z = rna_tf32(y.z + half_dt * kv[2]);
            yt.w = rna_tf32(y.w + half_dt * kv[3]);
            *reinterpret_cast<float4*>(&g_acc[i])  = acv;
            *reinterpret_cast<float4*>(&g_ytmp[i]) = yt;
        } else if (mode == 1 || mode == 2) {
            float4 acv = *reinterpret_cast<const float4*>(&g_acc[i]);
            acv.x += 2.f * kv[0]; acv.y += 2.f * kv[1];
            acv.z += 2.f * kv[2]; acv.w += 2.f * kv[3];
            float step = (mode == 1) ? half_dt : dt;
            float4 yt;
            yt.x = rna_tf32(y.x + step * kv[0]);
            yt.y = rna_tf32(y.y + step * kv[1]);
            yt.z = rna_tf32(y.z + step * kv[2]);
            yt.w = rna_tf32(y.w + step * kv[3]);
            *reinterpret_cast<float4*>(&g_acc[i])  = acv;
            *reinterpret_cast<float4*>(&g_ytmp[i]) = yt;
        } else if (mode == 3) {
            float4 acv = *reinterpret_cast<const float4*>(&g_acc[i]);
            float4 yn, yr;
            yn.x = y.x + sixth_dt * (acv.x + kv[0]);
            yn.y = y.y + sixth_dt * (acv.y + kv[1]);
            yn.z = y.z + sixth_dt * (acv.z + kv[2]);
            yn.w = y.w + sixth_dt * (acv.w + kv[3]);
            yr.x = rna_tf32(yn.x); yr.y = rna_tf32(yn.y);
            yr.z = rna_tf32(yn.z); yr.w = rna_tf32(yn.w);
            *reinterpret_cast<float4*>(&g_y[i])  = yn;
            *reinterpret_cast<float4*>(&g_yr[i]) = yr;
        } else {
            float4 acv = *reinterpret_cast<const float4*>(&g_acc[i]);
            float4 o;
            o.x = y.x + sixth_dt * (acv.x + kv[0]);
            o.y = y.y + sixth_dt * (acv.y + kv[1]);
            o.z = y.z + sixth_dt * (acv.z + kv[2]);
            o.w = y.w + sixth_dt * (acv.w + kv[3]);
            *reinterpret_cast<float4*>(&yout[i]) = o;
        }
    }
}

// ---------------------------------------------------------------------------
extern "C" void kernel_launch(void* const* d_in, const int* in_sizes, int n_in,
                              void* d_out, int out_size)
{
    const float* x  = (const float*)d_in[0];   // [1024, 512]
    const float* W1 = (const float*)d_in[1];   // [512, 2048]
    const float* b1 = (const float*)d_in[2];   // [2048]
    const float* W2 = (const float*)d_in[3];   // [2048, 512]
    const float* b2 = (const float*)d_in[4];   // [512]
    float* out = (float*)d_out;                // [1024, 512]

    const float dt = 1.0f / (float)NSTEPS;

    init_y_kernel<<<(B_ * D_ + 255) / 256, 256>>>(x);
    prep_weights_kernel<<<(D_ * H_ + 255) / 256, 256>>>(W1, W2);

    dim3 grid1(H_ / 128, B_ / 64);        // (16,16) = 256 CTAs
    dim3 grid2(D_ / 128, B_ / 64, 4);     // (4,16,4) = 256 CTAs

    for (int s = 0; s < NSTEPS; s++) {
        float t = dt * (float)s;

        gemm1_tanh  <<<grid1, 256>>>(b1, t, /*in_sel=*/0);
        gemm2_splitk<<<grid2, 256>>>(b2, dt, /*mode=*/0, out);

        gemm1_tanh  <<<grid1, 256>>>(b1, t + 0.5f * dt, /*in_sel=*/1);
        gemm2_splitk<<<grid2, 256>>>(b2, dt, /*mode=*/1, out);

        gemm1_tanh  <<<grid1, 256>>>(b1, t + 0.5f * dt, /*in_sel=*/1);
        gemm2_splitk<<<grid2, 256>>>(b2, dt, /*mode=*/2, out);

        gemm1_tanh  <<<grid1, 256>>>(b1, t + dt, /*in_sel=*/1);
        int mode = (s == NSTEPS - 1) ? 4 : 3;
        gemm2_splitk<<<grid2, 256>>>(b2, dt, mode, out);
    }
}

// round 10
// speedup vs baseline: 1.0107x; 1.0107x over previous
#include <cuda_runtime.h>
#include <math.h>

// Problem dims (fixed by the reference)
#define B_  1024
#define D_  512
#define H_  2048
#define NSTEPS 16

// -------- device scratch (allocation-free: static __device__ globals) --------
__device__ float g_y   [B_ * D_];      // current state y (exact fp32)
__device__ float g_yr  [B_ * D_];      // RNA-tf32-rounded copy of y (MMA input)
__device__ float g_ytmp[B_ * D_];      // RNA-rounded y + c*k (MMA input)
__device__ float g_acc [B_ * D_];      // RK4 accumulator (exact fp32)
__device__ float g_h   [B_ * H_];      // RNA-rounded tanh activations
__device__ float g_W1r [D_ * H_];      // RNA-rounded W1
__device__ float g_W2r [H_ * D_];      // RNA-rounded W2
__device__ float g_part[4][B_ * D_];   // split-K partials for GEMM2

// ---------------------------------------------------------------------------
__device__ __forceinline__ float rna_tf32(float x) {
    unsigned r;
    asm("cvt.rna.tf32.f32 %0, %1;" : "=r"(r) : "f"(x));
    return __uint_as_float(r);
}
__device__ __forceinline__ float fast_tanh(float x) {
    float y;
    asm("tanh.approx.f32 %0, %1;" : "=f"(y) : "f"(x));
    return y;
}
// mma.sync m16n8k8 tf32: D = A@B + C, fp32 accumulate. Inputs already tf32-exact.
__device__ __forceinline__ void mma_tf32(float* c, const unsigned* a, const unsigned* b) {
    asm volatile(
        "mma.sync.aligned.m16n8k8.row.col.f32.tf32.tf32.f32 "
        "{%0,%1,%2,%3}, {%4,%5,%6,%7}, {%8,%9}, {%0,%1,%2,%3};"
        : "+f"(c[0]), "+f"(c[1]), "+f"(c[2]), "+f"(c[3])
        : "r"(a[0]), "r"(a[1]), "r"(a[2]), "r"(a[3]),
          "r"(b[0]), "r"(b[1]));
}
__device__ __forceinline__ void cp_async16(float* smem_dst, const float* gmem_src) {
    unsigned s = (unsigned)__cvta_generic_to_shared(smem_dst);
    asm volatile("cp.async.ca.shared.global [%0], [%1], 16;\n" :: "r"(s), "l"(gmem_src));
}
__device__ __forceinline__ void cp_commit() {
    asm volatile("cp.async.commit_group;\n");
}
template <int N>
__device__ __forceinline__ void cp_wait() {
    asm volatile("cp.async.wait_group %0;\n" :: "n"(N));
}

// ---------------------------------------------------------------------------
__global__ void init_y_kernel(const float* __restrict__ x) {
    int i = blockIdx.x * blockDim.x + threadIdx.x;
    if (i < B_ * D_) {
        float v = x[i];
        g_y[i]  = v;
        g_yr[i] = rna_tf32(v);
    }
}
__global__ void prep_weights_kernel(const float* __restrict__ W1,
                                    const float* __restrict__ W2) {
    int i = blockIdx.x * blockDim.x + threadIdx.x;
    if (i < D_ * H_) {
        g_W1r[i] = rna_tf32(W1[i]);
        g_W2r[i] = rna_tf32(W2[i]);
    }
}

// ---------------------------------------------------------------------------
// GEMM1:  g_h[1024,2048] = rna( tanh( Ain[1024,512] @ W1r + b1 + t ) )
//   CTA 64x64, BK=16, 128 threads = 4 warps (2M x 2N), warp tile 32x32.
//   3-stage single-sync cp.async. Grid (32,16) = 512 CTAs -> ONE wave,
//   3-4 CTAs/SM (smem 28.5KB, ~62 regs -> up to 7 resident).
//   SMEM: As stride 20 (bank 20g+t4 distinct), Bs stride 72 (bank 8t4+g distinct).
__global__ __launch_bounds__(128) void gemm1_tanh(
    const float* __restrict__ b1, float t, int in_sel)
{
    __shared__ float As[3][64 * 20];
    __shared__ float Bs[3][16 * 72];

    const float* __restrict__ Ain = in_sel ? g_ytmp : g_yr;
    const float* __restrict__ W1  = g_W1r;

    const int tid  = threadIdx.x;
    const int lane = tid & 31;
    const int warp = tid >> 5;
    const int g    = lane >> 2;
    const int t4   = lane & 3;
    const int wm   = warp & 1;      // m offset wm*32
    const int wn   = warp >> 1;     // n offset wn*32

    const int bn0 = blockIdx.x * 64;
    const int bm0 = blockIdx.y * 64;

    // A: 64x16 = 256 chunks -> 2/thread.  B: 16x64 = 256 chunks -> 2/thread.
    auto load_slab = [&](int k0, int s) {
#pragma unroll
        for (int i = 0; i < 2; i++) {
            int id = tid + 128 * i;
            int r = id >> 2, c = (id & 3) * 4;
            cp_async16(&As[s][r * 20 + c], &Ain[(size_t)(bm0 + r) * D_ + k0 + c]);
        }
#pragma unroll
        for (int i = 0; i < 2; i++) {
            int id = tid + 128 * i;
            int r = id >> 4, c = (id & 15) * 4;
            cp_async16(&Bs[s][r * 72 + c], &W1[(size_t)(k0 + r) * H_ + bn0 + c]);
        }
        cp_commit();
    };

    float c[2][4][4];
#pragma unroll
    for (int i = 0; i < 2; i++)
#pragma unroll
        for (int j = 0; j < 4; j++)
#pragma unroll
            for (int e = 0; e < 4; e++) c[i][j][e] = 0.f;

    const int NS = D_ / 16;   // 32 slabs
    load_slab(0, 0);
    load_slab(16, 1);

    for (int si = 0; si < NS; si++) {
        if (si + 1 < NS) cp_wait<1>(); else cp_wait<0>();
        __syncthreads();
        if (si + 2 < NS) load_slab((si + 2) * 16, (si + 2) % 3);

        const unsigned* Asu = reinterpret_cast<const unsigned*>(As[si % 3]);
        const unsigned* Bsu = reinterpret_cast<const unsigned*>(Bs[si % 3]);
#pragma unroll
        for (int kk = 0; kk < 16; kk += 8) {
            unsigned a[2][4], b[4][2];
#pragma unroll
            for (int mt = 0; mt < 2; mt++) {
                int m0 = wm * 32 + mt * 16 + g;
                a[mt][0] = Asu[(m0)     * 20 + kk + t4];
                a[mt][1] = Asu[(m0 + 8) * 20 + kk + t4];
                a[mt][2] = Asu[(m0)     * 20 + kk + t4 + 4];
                a[mt][3] = Asu[(m0 + 8) * 20 + kk + t4 + 4];
            }
#pragma unroll
            for (int nt = 0; nt < 4; nt++) {
                int n0 = wn * 32 + nt * 8 + g;
                b[nt][0] = Bsu[(kk + t4)     * 72 + n0];
                b[nt][1] = Bsu[(kk + t4 + 4) * 72 + n0];
            }
#pragma unroll
            for (int mt = 0; mt < 2; mt++)
#pragma unroll
                for (int nt = 0; nt < 4; nt++)
                    mma_tf32(c[mt][nt], a[mt], b[nt]);
        }
    }

    // epilogue: rna(tanh(c + b1[n] + t)) -> g_h
#pragma unroll
    for (int mt = 0; mt < 2; mt++) {
        int row0 = bm0 + wm * 32 + mt * 16 + g;
#pragma unroll
        for (int nt = 0; nt < 4; nt++) {
            int col = bn0 + wn * 32 + nt * 8 + 2 * t4;
            float bb0 = b1[col] + t, bb1 = b1[col + 1] + t;
            float2 v0, v1;
            v0.x = rna_tf32(fast_tanh(c[mt][nt][0] + bb0));
            v0.y = rna_tf32(fast_tanh(c[mt][nt][1] + bb1));
            v1.x = rna_tf32(fast_tanh(c[mt][nt][2] + bb0));
            v1.y = rna_tf32(fast_tanh(c[mt][nt][3] + bb1));
            *reinterpret_cast<float2*>(&g_h[(size_t)row0 * H_ + col])       = v0;
            *reinterpret_cast<float2*>(&g_h[(size_t)(row0 + 8) * H_ + col]) = v1;
        }
    }
}

// ---------------------------------------------------------------------------
// GEMM2 split-K x4:
//   partial[z][1024,512] = g_h[:, z*512:(z+1)*512] @ W2r[z*512:(z+1)*512, :]
//   CTA 64x64, K-slice 512, BK=16, 128 threads = 4 warps (2M x 2N),
//   warp tile 32x32. Grid (8,16,4) = 512 CTAs -> ONE wave.
__global__ __launch_bounds__(128) void gemm2_splitk()
{
    __shared__ float As[3][64 * 20];
    __shared__ float Bs[3][16 * 72];

    const float* __restrict__ W2 = g_W2r;

    const int tid  = threadIdx.x;
    const int lane = tid & 31;
    const int warp = tid >> 5;
    const int g    = lane >> 2;
    const int t4   = lane & 3;
    const int wm   = warp & 1;      // m offset wm*32
    const int wn   = warp >> 1;     // n offset wn*32

    const int bn0 = blockIdx.x * 64;
    const int bm0 = blockIdx.y * 64;
    const int kb  = blockIdx.z * (H_ / 4);   // K-slice base

    auto load_slab = [&](int k0, int s) {
#pragma unroll
        for (int i = 0; i < 2; i++) {
            int id = tid + 128 * i;
            int r = id >> 2, c = (id & 3) * 4;
            cp_async16(&As[s][r * 20 + c],
                       &g_h[(size_t)(bm0 + r) * H_ + kb + k0 + c]);
        }
#pragma unroll
        for (int i = 0; i < 2; i++) {
            int id = tid + 128 * i;
            int r = id >> 4, c = (id & 15) * 4;
            cp_async16(&Bs[s][r * 72 + c],
                       &W2[(size_t)(kb + k0 + r) * D_ + bn0 + c]);
        }
        cp_commit();
    };

    float c[2][4][4];
#pragma unroll
    for (int i = 0; i < 2; i++)
#pragma unroll
        for (int j = 0; j < 4; j++)
#pragma unroll
            for (int e = 0; e < 4; e++) c[i][j][e] = 0.f;

    const int NS = (H_ / 4) / 16;   // 32 slabs
    load_slab(0, 0);
    load_slab(16, 1);

    for (int si = 0; si < NS; si++) {
        if (si + 1 < NS) cp_wait<1>(); else cp_wait<0>();
        __syncthreads();
        if (si + 2 < NS) load_slab((si + 2) * 16, (si + 2) % 3);

        const unsigned* Asu = reinterpret_cast<const unsigned*>(As[si % 3]);
        const unsigned* Bsu = reinterpret_cast<const unsigned*>(Bs[si % 3]);
#pragma unroll
        for (int kk = 0; kk < 16; kk += 8) {
            unsigned a[2][4], b[4][2];
#pragma unroll
            for (int mt = 0; mt < 2; mt++) {
                int m0 = wm * 32 + mt * 16 + g;
                a[mt][0] = Asu[(m0)     * 20 + kk + t4];
                a[mt][1] = Asu[(m0 + 8) * 20 + kk + t4];
                a[mt][2] = Asu[(m0)     * 20 + kk + t4 + 4];
                a[mt][3] = Asu[(m0 + 8) * 20 + kk + t4 + 4];
            }
#pragma unroll
            for (int nt = 0; nt < 4; nt++) {
                int n0 = wn * 32 + nt * 8 + g;
                b[nt][0] = Bsu[(kk + t4)     * 72 + n0];
                b[nt][1] = Bsu[(kk + t4 + 4) * 72 + n0];
            }
#pragma unroll
            for (int mt = 0; mt < 2; mt++)
#pragma unroll
                for (int nt = 0; nt < 4; nt++)
                    mma_tf32(c[mt][nt], a[mt], b[nt]);
        }
    }

    // write raw partial tile
    float* __restrict__ P = g_part[blockIdx.z];
#pragma unroll
    for (int mt = 0; mt < 2; mt++) {
        int row0 = bm0 + wm * 32 + mt * 16 + g;
#pragma unroll
        for (int nt = 0; nt < 4; nt++) {
            int col = bn0 + wn * 32 + nt * 8 + 2 * t4;
            *reinterpret_cast<float2*>(&P[(size_t)row0 * D_ + col]) =
                make_float2(c[mt][nt][0], c[mt][nt][1]);
            *reinterpret_cast<float2*>(&P[(size_t)(row0 + 8) * D_ + col]) =
                make_float2(c[mt][nt][2], c[mt][nt][3]);
        }
    }
}

// ---------------------------------------------------------------------------
// RK4 epilogue: kv = sum of 4 partials + b2; apply stage update.
// mode: 0 k1 / 1 k2 / 2 k3 / 3 k4 / 4 k4-final(write d_out)
__global__ __launch_bounds__(256) void rk4_epi(
    const float* __restrict__ b2, float dt, int mode, float* __restrict__ yout)
{
    const int i4 = blockIdx.x * blockDim.x + threadIdx.x;   // 0..131071
    const int i  = i4 * 4;
    const int col = i & (D_ - 1);

    float4 p0 = *reinterpret_cast<const float4*>(&g_part[0][i]);
    float4 p1 = *reinterpret_cast<const float4*>(&g_part[1][i]);
    float4 p2 = *reinterpret_cast<const float4*>(&g_part[2][i]);
    float4 p3 = *reinterpret_cast<const float4*>(&g_part[3][i]);
    float4 bb = *reinterpret_cast<const float4*>(&b2[col]);

    float kv[4];
    kv[0] = p0.x + p1.x + p2.x + p3.x + bb.x;
    kv[1] = p0.y + p1.y + p2.y + p3.y + bb.y;
    kv[2] = p0.z + p1.z + p2.z + p3.z + bb.z;
    kv[3] = p0.w + p1.w + p2.w + p3.w + bb.w;

    const float half_dt  = 0.5f * dt;
    const float sixth_dt = dt * (1.0f / 6.0f);

    float4 y = *reinterpret_cast<const float4*>(&g_y[i]);
    float yv[4] = {y.x, y.y, y.z, y.w};

    if (mode == 0) {
        float4 ac, yt;
        ac.x = kv[0]; ac.y = kv[1]; ac.z = kv[2]; ac.w = kv[3];
        yt.x = rna_tf32(yv[0] + half_dt * kv[0]);
        yt.y = rna_tf32(yv[1] + half_dt * kv[1]);
        yt.z = rna_tf32(yv[2] + half_dt * kv[2]);
        yt.w = rna_tf32(yv[3] + half_dt * kv[3]);
        *reinterpret_cast<float4*>(&g_acc[i])  = ac;
        *reinterpret_cast<float4*>(&g_ytmp[i]) = yt;
    } else if (mode == 1 || mode == 2) {
        float4 ac = *reinterpret_cast<const float4*>(&g_acc[i]);
        ac.x += 2.f * kv[0]; ac.y += 2.f * kv[1];
        ac.z += 2.f * kv[2]; ac.w += 2.f * kv[3];
        float step = (mode == 1) ? half_dt : dt;
        float4 yt;
        yt.x = rna_tf32(yv[0] + step * kv[0]);
        yt.y = rna_tf32(yv[1] + step * kv[1]);
        yt.z = rna_tf32(yv[2] + step * kv[2]);
        yt.w = rna_tf32(yv[3] + step * kv[3]);
        *reinterpret_cast<float4*>(&g_acc[i])  = ac;
        *reinterpret_cast<float4*>(&g_ytmp[i]) = yt;
    } else if (mode == 3) {
        float4 ac = *reinterpret_cast<const float4*>(&g_acc[i]);
        float4 yn, yr;
        yn.x = yv[0] + sixth_dt * (ac.x + kv[0]);
        yn.y = yv[1] + sixth_dt * (ac.y + kv[1]);
        yn.z = yv[2] + sixth_dt * (ac.z + kv[2]);
        yn.w = yv[3] + sixth_dt * (ac.w + kv[3]);
        yr.x = rna_tf32(yn.x); yr.y = rna_tf32(yn.y);
        yr.z = rna_tf32(yn.z); yr.w = rna_tf32(yn.w);
        *reinterpret_cast<float4*>(&g_y[i])  = yn;
        *reinterpret_cast<float4*>(&g_yr[i]) = yr;
    } else {
        float4 ac = *reinterpret_cast<const float4*>(&g_acc[i]);
        float4 o;
        o.x = yv[0] + sixth_dt * (ac.x + kv[0]);
        o.y = yv[1] + sixth_dt * (ac.y + kv[1]);
        o.z = yv[2] + sixth_dt * (ac.z + kv[2]);
        o.w = yv[3] + sixth_dt * (ac.w + kv[3]);
        *reinterpret_cast<float4*>(&yout[i]) = o;
    }
}

// ---------------------------------------------------------------------------
extern "C" void kernel_launch(void* const* d_in, const int* in_sizes, int n_in,
                              void* d_out, int out_size)
{
    const float* x  = (const float*)d_in[0];   // [1024, 512]
    const float* W1 = (const float*)d_in[1];   // [512, 2048]
    const float* b1 = (const float*)d_in[2];   // [2048]
    const float* W2 = (const float*)d_in[3];   // [2048, 512]
    const float* b2 = (const float*)d_in[4];   // [512]
    float* out = (float*)d_out;                // [1024, 512]

    const float dt = 1.0f / (float)NSTEPS;

    init_y_kernel<<<(B_ * D_ + 255) / 256, 256>>>(x);
    prep_weights_kernel<<<(D_ * H_ + 255) / 256, 256>>>(W1, W2);

    dim3 grid1(H_ / 64, B_ / 64);         // (32,16)  = 512 CTAs, one wave
    dim3 grid2(D_ / 64, B_ / 64, 4);      // (8,16,4) = 512 CTAs, one wave
    dim3 gridE((B_ * D_ / 4) / 256);      // 512 blocks

    for (int s = 0; s < NSTEPS; s++) {
        float t = dt * (float)s;

        gemm1_tanh  <<<grid1, 128>>>(b1, t, /*in_sel=*/0);
        gemm2_splitk<<<grid2, 128>>>();
        rk4_epi     <<<gridE, 256>>>(b2, dt, /*mode=*/0, out);

        gemm1_tanh  <<<grid1, 128>>>(b1, t + 0.5f * dt, /*in_sel=*/1);
        gemm2_splitk<<<grid2, 128>>>();
        rk4_epi     <<<gridE, 256>>>(b2, dt, /*mode=*/1, out);

        gemm1_tanh  <<<grid1, 128>>>(b1, t + 0.5f * dt, /*in_sel=*/1);
        gemm2_splitk<<<grid2, 128>>>();
        rk4_epi     <<<gridE, 256>>>(b2, dt, /*mode=*/2, out);

        gemm1_tanh  <<<grid1, 128>>>(b1, t + dt, /*in_sel=*/1);
        gemm2_splitk<<<grid2, 128>>>();
        int mode = (s == NSTEPS - 1) ? 4 : 3;
        rk4_epi     <<<gridE, 256>>>(b2, dt, mode, out);
    }
}

// round 11
// speedup vs baseline: 1.1684x; 1.1560x over previous
#include <cuda_runtime.h>
#include <math.h>

// Problem dims (fixed by the reference)
#define B_  1024
#define D_  512
#define H_  2048
#define NSTEPS 16

// -------- device scratch (allocation-free: static __device__ globals) --------
__device__ float g_y   [B_ * D_];      // current state y (exact fp32)
__device__ float g_yr  [B_ * D_];      // RNA-tf32-rounded copy of y (MMA input)
__device__ float g_ytmp[B_ * D_];      // RNA-rounded y + c*k (MMA input)
__device__ float g_acc [B_ * D_];      // RK4 accumulator (exact fp32)
__device__ float g_h   [B_ * H_];      // RNA-rounded tanh activations
__device__ float g_W1r [D_ * H_];      // RNA-rounded W1
__device__ float g_W2r [H_ * D_];      // RNA-rounded W2
__device__ float g_part[4][B_ * D_];   // split-K partials for GEMM2

// ---------------------------------------------------------------------------
__device__ __forceinline__ float rna_tf32(float x) {
    unsigned r;
    asm("cvt.rna.tf32.f32 %0, %1;" : "=r"(r) : "f"(x));
    return __uint_as_float(r);
}
__device__ __forceinline__ float fast_tanh(float x) {
    float y;
    asm("tanh.approx.f32 %0, %1;" : "=f"(y) : "f"(x));
    return y;
}
// mma.sync m16n8k8 tf32: D = A@B + C, fp32 accumulate. Inputs already tf32-exact.
__device__ __forceinline__ void mma_tf32(float* c, const unsigned* a, const unsigned* b) {
    asm volatile(
        "mma.sync.aligned.m16n8k8.row.col.f32.tf32.tf32.f32 "
        "{%0,%1,%2,%3}, {%4,%5,%6,%7}, {%8,%9}, {%0,%1,%2,%3};"
        : "+f"(c[0]), "+f"(c[1]), "+f"(c[2]), "+f"(c[3])
        : "r"(a[0]), "r"(a[1]), "r"(a[2]), "r"(a[3]),
          "r"(b[0]), "r"(b[1]));
}
__device__ __forceinline__ void cp_async16(float* smem_dst, const float* gmem_src) {
    unsigned s = (unsigned)__cvta_generic_to_shared(smem_dst);
    asm volatile("cp.async.ca.shared.global [%0], [%1], 16;\n" :: "r"(s), "l"(gmem_src));
}
__device__ __forceinline__ void cp_commit() {
    asm volatile("cp.async.commit_group;\n");
}
template <int N>
__device__ __forceinline__ void cp_wait() {
    asm volatile("cp.async.wait_group %0;\n" :: "n"(N));
}

// ---------------------------------------------------------------------------
__global__ void init_y_kernel(const float* __restrict__ x) {
    int i = blockIdx.x * blockDim.x + threadIdx.x;
    if (i < B_ * D_) {
        float v = x[i];
        g_y[i]  = v;
        g_yr[i] = rna_tf32(v);
    }
}
__global__ void prep_weights_kernel(const float* __restrict__ W1,
                                    const float* __restrict__ W2) {
    int i = blockIdx.x * blockDim.x + threadIdx.x;
    if (i < D_ * H_) {
        g_W1r[i] = rna_tf32(W1[i]);
        g_W2r[i] = rna_tf32(W2[i]);
    }
}

// ---------------------------------------------------------------------------
// SMEM layout (floats), dynamic 56,832 B per CTA:
//   A(s) at s*2560   (128 rows x stride 20)  s = 0..2
//   B(s) at 7680 + s*2176 (16 rows x stride 136)
// Frag banks: A -> 20g + t4 (32 distinct); B -> 8*t4 + g (32 distinct).
#define ASLAB 2560
#define BOFF  7680
#define BSLAB 2176

// ---------------------------------------------------------------------------
// GEMM1:  g_h[1024,2048] = rna( tanh( Ain[1024,512] @ W1r + b1 + t ) )
//   CTA 128x128, BK=16, 256 threads = 8 warps (2M x 4N), warp tile 64x32.
//   LDS/MMA = 1.5 (A 16 + B 8 LDS per 16 MMAs per k8).
//   3-stage single-sync cp.async. Grid (16,8) = 128 CTAs.
__global__ __launch_bounds__(256) void gemm1_tanh(
    const float* __restrict__ b1, float t, int in_sel)
{
    extern __shared__ float S[];

    const float* __restrict__ Ain = in_sel ? g_ytmp : g_yr;
    const float* __restrict__ W1  = g_W1r;

    const int tid  = threadIdx.x;
    const int lane = tid & 31;
    const int warp = tid >> 5;
    const int g    = lane >> 2;
    const int t4   = lane & 3;
    const int wm   = warp & 1;      // m offset wm*64
    const int wn   = warp >> 1;     // n offset wn*32

    const int bn0 = blockIdx.x * 128;
    const int bm0 = blockIdx.y * 128;

    // A: 128x16 = 512 chunks -> 2/thread.  B: 16x128 = 512 chunks -> 2/thread.
    auto load_slab = [&](int k0, int s) {
#pragma unroll
        for (int i = 0; i < 2; i++) {
            int id = tid + 256 * i;
            int r = id >> 2, c = (id & 3) * 4;
            cp_async16(&S[s * ASLAB + r * 20 + c],
                       &Ain[(size_t)(bm0 + r) * D_ + k0 + c]);
        }
#pragma unroll
        for (int i = 0; i < 2; i++) {
            int id = tid + 256 * i;
            int r = id >> 5, c = (id & 31) * 4;
            cp_async16(&S[BOFF + s * BSLAB + r * 136 + c],
                       &W1[(size_t)(k0 + r) * H_ + bn0 + c]);
        }
        cp_commit();
    };

    float c[4][4][4];
#pragma unroll
    for (int i = 0; i < 4; i++)
#pragma unroll
        for (int j = 0; j < 4; j++)
#pragma unroll
            for (int e = 0; e < 4; e++) c[i][j][e] = 0.f;

    const int NS = D_ / 16;   // 32 slabs
    load_slab(0, 0);
    load_slab(16, 1);

    for (int si = 0; si < NS; si++) {
        if (si + 1 < NS) cp_wait<1>(); else cp_wait<0>();
        __syncthreads();
        if (si + 2 < NS) load_slab((si + 2) * 16, (si + 2) % 3);

        const unsigned* Asu = reinterpret_cast<const unsigned*>(&S[(si % 3) * ASLAB]);
        const unsigned* Bsu = reinterpret_cast<const unsigned*>(&S[BOFF + (si % 3) * BSLAB]);
#pragma unroll
        for (int kk = 0; kk < 16; kk += 8) {
            unsigned a[4][4], b[4][2];
#pragma unroll
            for (int mt = 0; mt < 4; mt++) {
                int m0 = wm * 64 + mt * 16 + g;
                a[mt][0] = Asu[(m0)     * 20 + kk + t4];
                a[mt][1] = Asu[(m0 + 8) * 20 + kk + t4];
                a[mt][2] = Asu[(m0)     * 20 + kk + t4 + 4];
                a[mt][3] = Asu[(m0 + 8) * 20 + kk + t4 + 4];
            }
#pragma unroll
            for (int nt = 0; nt < 4; nt++) {
                int n0 = wn * 32 + nt * 8 + g;
                b[nt][0] = Bsu[(kk + t4)     * 136 + n0];
                b[nt][1] = Bsu[(kk + t4 + 4) * 136 + n0];
            }
#pragma unroll
            for (int mt = 0; mt < 4; mt++)
#pragma unroll
                for (int nt = 0; nt < 4; nt++)
                    mma_tf32(c[mt][nt], a[mt], b[nt]);
        }
    }

    // epilogue: rna(tanh(c + b1[n] + t)) -> g_h
#pragma unroll
    for (int mt = 0; mt < 4; mt++) {
        int row0 = bm0 + wm * 64 + mt * 16 + g;
#pragma unroll
        for (int nt = 0; nt < 4; nt++) {
            int col = bn0 + wn * 32 + nt * 8 + 2 * t4;
            float bb0 = b1[col] + t, bb1 = b1[col + 1] + t;
            float2 v0, v1;
            v0.x = rna_tf32(fast_tanh(c[mt][nt][0] + bb0));
            v0.y = rna_tf32(fast_tanh(c[mt][nt][1] + bb1));
            v1.x = rna_tf32(fast_tanh(c[mt][nt][2] + bb0));
            v1.y = rna_tf32(fast_tanh(c[mt][nt][3] + bb1));
            *reinterpret_cast<float2*>(&g_h[(size_t)row0 * H_ + col])       = v0;
            *reinterpret_cast<float2*>(&g_h[(size_t)(row0 + 8) * H_ + col]) = v1;
        }
    }
}

// ---------------------------------------------------------------------------
// GEMM2 split-K x4, identical geometry to GEMM1:
//   partial[z][1024,512] = g_h[:, z*512:(z+1)*512] @ W2r[z*512:(z+1)*512, :]
//   CTA 128x128, K-slice 512, BK=16, 256 threads, warp tile 64x32.
//   Grid (4,8,4) = 128 CTAs.
__global__ __launch_bounds__(256) void gemm2_splitk()
{
    extern __shared__ float S[];

    const float* __restrict__ W2 = g_W2r;

    const int tid  = threadIdx.x;
    const int lane = tid & 31;
    const int warp = tid >> 5;
    const int g    = lane >> 2;
    const int t4   = lane & 3;
    const int wm   = warp & 1;      // m offset wm*64
    const int wn   = warp >> 1;     // n offset wn*32

    const int bn0 = blockIdx.x * 128;
    const int bm0 = blockIdx.y * 128;
    const int kb  = blockIdx.z * (H_ / 4);   // K-slice base

    auto load_slab = [&](int k0, int s) {
#pragma unroll
        for (int i = 0; i < 2; i++) {
            int id = tid + 256 * i;
            int r = id >> 2, c = (id & 3) * 4;
            cp_async16(&S[s * ASLAB + r * 20 + c],
                       &g_h[(size_t)(bm0 + r) * H_ + kb + k0 + c]);
        }
#pragma unroll
        for (int i = 0; i < 2; i++) {
            int id = tid + 256 * i;
            int r = id >> 5, c = (id & 31) * 4;
            cp_async16(&S[BOFF + s * BSLAB + r * 136 + c],
                       &W2[(size_t)(kb + k0 + r) * D_ + bn0 + c]);
        }
        cp_commit();
    };

    float c[4][4][4];
#pragma unroll
    for (int i = 0; i < 4; i++)
#pragma unroll
        for (int j = 0; j < 4; j++)
#pragma unroll
            for (int e = 0; e < 4; e++) c[i][j][e] = 0.f;

    const int NS = (H_ / 4) / 16;   // 32 slabs
    load_slab(0, 0);
    load_slab(16, 1);

    for (int si = 0; si < NS; si++) {
        if (si + 1 < NS) cp_wait<1>(); else cp_wait<0>();
        __syncthreads();
        if (si + 2 < NS) load_slab((si + 2) * 16, (si + 2) % 3);

        const unsigned* Asu = reinterpret_cast<const unsigned*>(&S[(si % 3) * ASLAB]);
        const unsigned* Bsu = reinterpret_cast<const unsigned*>(&S[BOFF + (si % 3) * BSLAB]);
#pragma unroll
        for (int kk = 0; kk < 16; kk += 8) {
            unsigned a[4][4], b[4][2];
#pragma unroll
            for (int mt = 0; mt < 4; mt++) {
                int m0 = wm * 64 + mt * 16 + g;
                a[mt][0] = Asu[(m0)     * 20 + kk + t4];
                a[mt][1] = Asu[(m0 + 8) * 20 + kk + t4];
                a[mt][2] = Asu[(m0)     * 20 + kk + t4 + 4];
                a[mt][3] = Asu[(m0 + 8) * 20 + kk + t4 + 4];
            }
#pragma unroll
            for (int nt = 0; nt < 4; nt++) {
                int n0 = wn * 32 + nt * 8 + g;
                b[nt][0] = Bsu[(kk + t4)     * 136 + n0];
                b[nt][1] = Bsu[(kk + t4 + 4) * 136 + n0];
            }
#pragma unroll
            for (int mt = 0; mt < 4; mt++)
#pragma unroll
                for (int nt = 0; nt < 4; nt++)
                    mma_tf32(c[mt][nt], a[mt], b[nt]);
        }
    }

    // write raw partial tile
    float* __restrict__ P = g_part[blockIdx.z];
#pragma unroll
    for (int mt = 0; mt < 4; mt++) {
        int row0 = bm0 + wm * 64 + mt * 16 + g;
#pragma unroll
        for (int nt = 0; nt < 4; nt++) {
            int col = bn0 + wn * 32 + nt * 8 + 2 * t4;
            *reinterpret_cast<float2*>(&P[(size_t)row0 * D_ + col]) =
                make_float2(c[mt][nt][0], c[mt][nt][1]);
            *reinterpret_cast<float2*>(&P[(size_t)(row0 + 8) * D_ + col]) =
                make_float2(c[mt][nt][2], c[mt][nt][3]);
        }
    }
}

// ---------------------------------------------------------------------------
// RK4 epilogue: kv = sum of 4 partials + b2; apply stage update.
// mode: 0 k1 / 1 k2 / 2 k3 / 3 k4 / 4 k4-final(write d_out)
__global__ __launch_bounds__(256) void rk4_epi(
    const float* __restrict__ b2, float dt, int mode, float* __restrict__ yout)
{
    const int i4 = blockIdx.x * blockDim.x + threadIdx.x;   // 0..131071
    const int i  = i4 * 4;
    const int col = i & (D_ - 1);

    float4 p0 = *reinterpret_cast<const float4*>(&g_part[0][i]);
    float4 p1 = *reinterpret_cast<const float4*>(&g_part[1][i]);
    float4 p2 = *reinterpret_cast<const float4*>(&g_part[2][i]);
    float4 p3 = *reinterpret_cast<const float4*>(&g_part[3][i]);
    float4 bb = *reinterpret_cast<const float4*>(&b2[col]);

    float kv[4];
    kv[0] = p0.x + p1.x + p2.x + p3.x + bb.x;
    kv[1] = p0.y + p1.y + p2.y + p3.y + bb.y;
    kv[2] = p0.z + p1.z + p2.z + p3.z + bb.z;
    kv[3] = p0.w + p1.w + p2.w + p3.w + bb.w;

    const float half_dt  = 0.5f * dt;
    const float sixth_dt = dt * (1.0f / 6.0f);

    float4 y = *reinterpret_cast<const float4*>(&g_y[i]);
    float yv[4] = {y.x, y.y, y.z, y.w};

    if (mode == 0) {
        float4 ac, yt;
        ac.x = kv[0]; ac.y = kv[1]; ac.z = kv[2]; ac.w = kv[3];
        yt.x = rna_tf32(yv[0] + half_dt * kv[0]);
        yt.y = rna_tf32(yv[1] + half_dt * kv[1]);
        yt.z = rna_tf32(yv[2] + half_dt * kv[2]);
        yt.w = rna_tf32(yv[3] + half_dt * kv[3]);
        *reinterpret_cast<float4*>(&g_acc[i])  = ac;
        *reinterpret_cast<float4*>(&g_ytmp[i]) = yt;
    } else if (mode == 1 || mode == 2) {
        float4 ac = *reinterpret_cast<const float4*>(&g_acc[i]);
        ac.x += 2.f * kv[0]; ac.y += 2.f * kv[1];
        ac.z += 2.f * kv[2]; ac.w += 2.f * kv[3];
        float step = (mode == 1) ? half_dt : dt;
        float4 yt;
        yt.x = rna_tf32(yv[0] + step * kv[0]);
        yt.y = rna_tf32(yv[1] + step * kv[1]);
        yt.z = rna_tf32(yv[2] + step * kv[2]);
        yt.w = rna_tf32(yv[3] + step * kv[3]);
        *reinterpret_cast<float4*>(&g_acc[i])  = ac;
        *reinterpret_cast<float4*>(&g_ytmp[i]) = yt;
    } else if (mode == 3) {
        float4 ac = *reinterpret_cast<const float4*>(&g_acc[i]);
        float4 yn, yr;
        yn.x = yv[0] + sixth_dt * (ac.x + kv[0]);
        yn.y = yv[1] + sixth_dt * (ac.y + kv[1]);
        yn.z = yv[2] + sixth_dt * (ac.z + kv[2]);
        yn.w = yv[3] + sixth_dt * (ac.w + kv[3]);
        yr.x = rna_tf32(yn.x); yr.y = rna_tf32(yn.y);
        yr.z = rna_tf32(yn.z); yr.w = rna_tf32(yn.w);
        *reinterpret_cast<float4*>(&g_y[i])  = yn;
        *reinterpret_cast<float4*>(&g_yr[i]) = yr;
    } else {
        float4 ac = *reinterpret_cast<const float4*>(&g_acc[i]);
        float4 o;
        o.x = yv[0] + sixth_dt * (ac.x + kv[0]);
        o.y = yv[1] + sixth_dt * (ac.y + kv[1]);
        o.z = yv[2] + sixth_dt * (ac.z + kv[2]);
        o.w = yv[3] + sixth_dt * (ac.w + kv[3]);
        *reinterpret_cast<float4*>(&yout[i]) = o;
    }
}

// ---------------------------------------------------------------------------
extern "C" void kernel_launch(void* const* d_in, const int* in_sizes, int n_in,
                              void* d_out, int out_size)
{
    const float* x  = (const float*)d_in[0];   // [1024, 512]
    const float* W1 = (const float*)d_in[1];   // [512, 2048]
    const float* b1 = (const float*)d_in[2];   // [2048]
    const float* W2 = (const float*)d_in[3];   // [2048, 512]
    const float* b2 = (const float*)d_in[4];   // [512]
    float* out = (float*)d_out;                // [1024, 512]

    const float dt = 1.0f / (float)NSTEPS;

    const int SMEM_G = (3 * ASLAB + 3 * BSLAB) * 4;   // 56,832 B
    cudaFuncSetAttribute(gemm1_tanh,  cudaFuncAttributeMaxDynamicSharedMemorySize, SMEM_G);
    cudaFuncSetAttribute(gemm2_splitk, cudaFuncAttributeMaxDynamicSharedMemorySize, SMEM_G);

    init_y_kernel<<<(B_ * D_ + 255) / 256, 256>>>(x);
    prep_weights_kernel<<<(D_ * H_ + 255) / 256, 256>>>(W1, W2);

    dim3 grid1(H_ / 128, B_ / 128);        // (16,8)  = 128 CTAs
    dim3 grid2(D_ / 128, B_ / 128, 4);     // (4,8,4) = 128 CTAs
    dim3 gridE((B_ * D_ / 4) / 256);       // 512 blocks

    for (int s = 0; s < NSTEPS; s++) {
        float t = dt * (float)s;

        gemm1_tanh  <<<grid1, 256, SMEM_G>>>(b1, t, /*in_sel=*/0);
        gemm2_splitk<<<grid2, 256, SMEM_G>>>();
        rk4_epi     <<<gridE, 256>>>(b2, dt, /*mode=*/0, out);

        gemm1_tanh  <<<grid1, 256, SMEM_G>>>(b1, t + 0.5f * dt, /*in_sel=*/1);
        gemm2_splitk<<<grid2, 256, SMEM_G>>>();
        rk4_epi     <<<gridE, 256>>>(b2, dt, /*mode=*/1, out);

        gemm1_tanh  <<<grid1, 256, SMEM_G>>>(b1, t + 0.5f * dt, /*in_sel=*/1);
        gemm2_splitk<<<grid2, 256, SMEM_G>>>();
        rk4_epi     <<<gridE, 256>>>(b2, dt, /*mode=*/2, out);

        gemm1_tanh  <<<grid1, 256, SMEM_G>>>(b1, t + dt, /*in_sel=*/1);
        gemm2_splitk<<<grid2, 256, SMEM_G>>>();
        int mode = (s == NSTEPS - 1) ? 4 : 3;
        rk4_epi     <<<gridE, 256>>>(b2, dt, mode, out);
    }
}